// round 13
// baseline (speedup 1.0000x reference)
#include <cuda_runtime.h>
#include <cstdint>

// out = mean( (box9(pred) - box9(target))^2 ), zero-padded on H,W.
// box9(pred)-box9(target) = box9(pred-target); separable 9x9 box.
//
// Warp-specialized: warp 8 = TMA producer (cp.async.bulk, 8KB 4-row copies,
// 3-slot unpadded ring per tensor), warps 0-7 = consumers (2 cols per thread,
// hsum via 4 warp shuffles + smem fixups for edge lanes, vertical 9-sum via
// 8-deep register ring). TH=64 -> 512 blocks (single wave), ~31 warps/SM.

#define Wd      512
#define Hd      512
#define TH      64
#define NSTRIP  8
#define NIMG    64
#define NBLK    (NSTRIP * NIMG)      // 512
#define GR      4                     // rows per slot
#define SLOTS   3
#define NGRP    18                    // 72 rows / GR
#define ROWB    2048                  // bytes per row (512 f32)
#define NTOT    16777216.0

#define BUF_FLOATS (SLOTS * GR * Wd)          // per tensor: 6144
#define BAR_OFF    (2 * BUF_FLOATS * 4)       // 49152 bytes
#define SMEM_BYTES (BAR_OFF + 64)             // + full[3], empty[3]

__device__ double       g_sum  = 0.0;
__device__ unsigned int g_done = 0;

static __device__ __forceinline__ uint32_t s2u(const void* p) {
    uint32_t a;
    asm("{ .reg .u64 t; cvta.to.shared.u64 t, %1; cvt.u32.u64 %0, t; }"
        : "=r"(a) : "l"(p));
    return a;
}
static __device__ __forceinline__ void mbar_init(uint32_t mb, uint32_t cnt) {
    asm volatile("mbarrier.init.shared.b64 [%0], %1;" :: "r"(mb), "r"(cnt) : "memory");
}
static __device__ __forceinline__ void mbar_expect_tx(uint32_t mb, uint32_t bytes) {
    asm volatile("mbarrier.arrive.expect_tx.shared.b64 _, [%0], %1;"
                 :: "r"(mb), "r"(bytes) : "memory");
}
static __device__ __forceinline__ void mbar_arrive(uint32_t mb) {
    asm volatile("mbarrier.arrive.release.cta.shared.b64 _, [%0];"
                 :: "r"(mb) : "memory");
}
static __device__ __forceinline__ void bulk_g2s(uint32_t dst, const void* src,
                                                uint32_t bytes, uint32_t mb) {
    asm volatile(
        "cp.async.bulk.shared::cta.global.mbarrier::complete_tx::bytes [%0], [%1], %2, [%3];"
        :: "r"(dst), "l"(src), "r"(bytes), "r"(mb) : "memory");
}
static __device__ __forceinline__ void mbar_wait(uint32_t mb, uint32_t parity) {
    asm volatile(
        "{\n\t"
        ".reg .pred P1;\n\t"
        "WL_%=:\n\t"
        "mbarrier.try_wait.parity.acquire.cta.shared::cta.b64 P1, [%0], %1, 0x989680;\n\t"
        "@P1 bra.uni WD_%=;\n\t"
        "bra.uni WL_%=;\n\t"
        "WD_%=:\n\t"
        "}"
        :: "r"(mb), "r"(parity) : "memory");
}

__global__ __launch_bounds__(288, 4)
void pooled_mse_kernel(const float* __restrict__ pred,
                       const float* __restrict__ target,
                       float* __restrict__ out) {
    extern __shared__ float sm[];
    float* pbuf = sm;                        // [SLOTS][GR][512]
    float* tbuf = sm + BUF_FLOATS;
    __shared__ float s_red[16];

    const uint32_t sbase = s2u(sm);
    const uint32_t bar   = sbase + BAR_OFF;  // full[s]=bar+8s, empty[s]=bar+24+8s

    const int tid  = threadIdx.x;
    const int lane = tid & 31;
    const int warp = tid >> 5;
    const int y0   = blockIdx.x * TH;
    const int img  = blockIdx.y;

    const float* pimg = pred   + (size_t)img * (Hd * Wd);
    const float* timg = target + (size_t)img * (Hd * Wd);

    if (tid == 0) {
        #pragma unroll
        for (int s = 0; s < SLOTS; s++) {
            mbar_init(bar + s * 8, 1);        // full: tx-based
            mbar_init(bar + 24 + s * 8, 8);   // empty: 8 consumer warps
        }
    }
    __syncthreads();

    float acc = 0.0f;

    if (tid < 256) {
        // ================= consumers: 2 cols per thread =================
        const int x0 = tid << 1;              // cols x0, x0+1
        float2 Hring[8];
        float2 vs = make_float2(0.f, 0.f);

        #pragma unroll 1
        for (int g0 = 0; g0 < NGRP; g0 += 6) {      // 3 chunks of 6 groups
            #pragma unroll
            for (int gi = 0; gi < 6; gi++) {
                const int g    = g0 + gi;
                const int slot = gi % 3;             // compile-time
                const uint32_t par = (gi >= 3) ? 1u : 0u;
                mbar_wait(bar + slot * 8, par);

                #pragma unroll
                for (int i = 0; i < GR; i++) {
                    const int rr   = gi * GR + i;    // compile-time 0..23
                    const int rabs = y0 - 4 + g * GR + i;
                    const bool valid = ((unsigned)rabs < (unsigned)Hd); // uniform

                    float2 hv = make_float2(0.f, 0.f);
                    if (valid) {
                        const float* prow = pbuf + (slot * GR + i) * Wd;
                        const float* trow = tbuf + (slot * GR + i) * Wd;
                        const float2 p = *(const float2*)(prow + x0);
                        const float2 t = *(const float2*)(trow + x0);
                        float2 d = make_float2(p.x - t.x, p.y - t.y);

                        // neighbors via shuffles (dist 1 and 2)
                        float2 u1, u2, n1, n2;
                        u1.x = __shfl_up_sync(0xFFFFFFFFu, d.x, 1);
                        u1.y = __shfl_up_sync(0xFFFFFFFFu, d.y, 1);
                        u2.x = __shfl_up_sync(0xFFFFFFFFu, d.x, 2);
                        u2.y = __shfl_up_sync(0xFFFFFFFFu, d.y, 2);
                        n1.x = __shfl_down_sync(0xFFFFFFFFu, d.x, 1);
                        n1.y = __shfl_down_sync(0xFFFFFFFFu, d.y, 1);
                        n2.x = __shfl_down_sync(0xFFFFFFFFu, d.x, 2);
                        n2.y = __shfl_down_sync(0xFFFFFFFFu, d.y, 2);

                        // edge-lane fixups from smem (raw rows are right there)
                        if (lane == 0) {
                            u1 = make_float2(0.f, 0.f);
                            u2 = make_float2(0.f, 0.f);
                            if (x0 != 0) {
                                const float2 pa = *(const float2*)(prow + x0 - 2);
                                const float2 ta = *(const float2*)(trow + x0 - 2);
                                u1 = make_float2(pa.x - ta.x, pa.y - ta.y);
                                const float2 pb = *(const float2*)(prow + x0 - 4);
                                const float2 tb = *(const float2*)(trow + x0 - 4);
                                u2 = make_float2(pb.x - tb.x, pb.y - tb.y);
                            }
                        } else if (lane == 1) {
                            u2 = make_float2(0.f, 0.f);
                            if (x0 >= 4) {
                                const float2 pb = *(const float2*)(prow + x0 - 4);
                                const float2 tb = *(const float2*)(trow + x0 - 4);
                                u2 = make_float2(pb.x - tb.x, pb.y - tb.y);
                            }
                        }
                        if (lane == 31) {
                            n1 = make_float2(0.f, 0.f);
                            n2 = make_float2(0.f, 0.f);
                            if (x0 + 2 < Wd) {
                                const float2 pa = *(const float2*)(prow + x0 + 2);
                                const float2 ta = *(const float2*)(trow + x0 + 2);
                                n1 = make_float2(pa.x - ta.x, pa.y - ta.y);
                                const float2 pb = *(const float2*)(prow + x0 + 4);
                                const float2 tb = *(const float2*)(trow + x0 + 4);
                                n2 = make_float2(pb.x - tb.x, pb.y - tb.y);
                            }
                        } else if (lane == 30) {
                            n2 = make_float2(0.f, 0.f);
                            if (x0 + 4 < Wd) {
                                const float2 pb = *(const float2*)(prow + x0 + 4);
                                const float2 tb = *(const float2*)(trow + x0 + 4);
                                n2 = make_float2(pb.x - tb.x, pb.y - tb.y);
                            }
                        }

                        const float h0 = ((u2.x + u2.y) + (u1.x + u1.y))
                                       + (d.x + d.y)
                                       + ((n1.x + n1.y) + n2.x);
                        const float h1 = h0 - u2.x + n2.y;
                        hv = make_float2(h0, h1);
                    }

                    // 8-deep ring, read-before-write (rr&7 compile-time:
                    // chunks are 24 rows, multiple of 8)
                    const float2 ho = Hring[rr & 7];
                    Hring[rr & 7] = hv;
                    vs.x += hv.x; vs.y += hv.y;
                    if (g * GR + i >= 8) {           // uniform
                        acc += vs.x * vs.x + vs.y * vs.y;
                        vs.x -= ho.x; vs.y -= ho.y;
                    }
                }
                if (lane == 0) mbar_arrive(bar + 24 + slot * 8);
            }
        }
    } else if (tid == 256) {
        // ================= producer =================
        asm volatile("fence.proxy.async.shared::cta;" ::: "memory");
        const uint32_t pbuf_u = sbase;
        const uint32_t tbuf_u = sbase + BUF_FLOATS * 4;
        #pragma unroll 1
        for (int g0 = 0; g0 < NGRP; g0 += 6) {
            #pragma unroll
            for (int gi = 0; gi < 6; gi++) {
                const int g    = g0 + gi;
                const int slot = gi % 3;
                const uint32_t par = (gi >= 3) ? 1u : 0u;
                // fresh-barrier trick: first 3 waits (parity 1) pass instantly
                mbar_wait(bar + 24 + slot * 8, 1u ^ par);

                const int rbase = y0 - 4 + GR * g;
                int i0 = rbase < 0 ? -rbase : 0;
                int i1 = (rbase + GR > Hd) ? (Hd - rbase) : GR;
                if (i1 < i0) i1 = i0;
                const int n = i1 - i0;
                const uint32_t mb = bar + slot * 8;
                mbar_expect_tx(mb, (uint32_t)(n * ROWB * 2));
                if (n > 0) {
                    const uint32_t off = (uint32_t)(slot * GR + i0) * ROWB;
                    const size_t gofs = (size_t)(rbase + i0) * Wd;
                    bulk_g2s(pbuf_u + off, pimg + gofs, (uint32_t)(n * ROWB), mb);
                    bulk_g2s(tbuf_u + off, timg + gofs, (uint32_t)(n * ROWB), mb);
                }
            }
        }
    }

    // ---- block reduction (9 warps) ----
    #pragma unroll
    for (int off = 16; off > 0; off >>= 1)
        acc += __shfl_xor_sync(0xFFFFFFFFu, acc, off);
    if (tid < 16) s_red[tid] = 0.0f;
    __syncthreads();
    if (lane == 0) s_red[warp] = acc;    // warp 8 (producer) writes 0
    __syncthreads();
    if (warp == 0) {
        float v = (lane < 16) ? s_red[lane] : 0.0f;
        #pragma unroll
        for (int off = 8; off > 0; off >>= 1)
            v += __shfl_xor_sync(0xFFFFFFFFu, v, off);
        if (lane == 0) {
            atomicAdd(&g_sum, (double)v);
            __threadfence();
            const unsigned old = atomicAdd(&g_done, 1u);
            if (old == NBLK - 1) {
                const double s = *((volatile double*)&g_sum);
                out[0] = (float)(s / (81.0 * 81.0) / NTOT);
                g_sum  = 0.0;                 // reset for next graph replay
                g_done = 0u;
            }
        }
    }
}

extern "C" void kernel_launch(void* const* d_in, const int* in_sizes, int n_in,
                              void* d_out, int out_size) {
    const float* pred   = (const float*)d_in[0];
    const float* target = (const float*)d_in[1];
    float* out = (float*)d_out;
    cudaFuncSetAttribute(pooled_mse_kernel,
                         cudaFuncAttributeMaxDynamicSharedMemorySize, SMEM_BYTES);
    dim3 grid(NSTRIP, NIMG);                  // 512 blocks: single wave
    pooled_mse_kernel<<<grid, 288, SMEM_BYTES>>>(pred, target, out);
}